// round 7
// baseline (speedup 1.0000x reference)
#include <cuda_runtime.h>
#include <cuda_bf16.h>
#include <cstdint>

#define NV 50000
#define NE 10000
#define NM 200000
#define DD 512
#define BN_EPS 1e-5f

// ---------------- scratch (static device globals; no allocation) ----------------
__device__ float g_Y[(size_t)NV * DD];            // GEMM output (pre-BN)
__device__ __nv_bfloat16 g_Xh[(size_t)NV * DD];   // hi bf16 split of X
__device__ __nv_bfloat16 g_Xl[(size_t)NV * DD];   // lo bf16 split of X
__device__ __nv_bfloat16 g_Wth[DD * DD];          // W^T hi split  [n][k]
__device__ __nv_bfloat16 g_Wtl[DD * DD];          // W^T lo split  [n][k]
__device__ float g_stats[2 * DD];
__device__ float g_scale[DD];
__device__ float g_shift[DD];
__device__ int   g_deg_e[NE];
__device__ int   g_deg_v[NV];
__device__ int   g_cur_e[NE];
__device__ int   g_cur_v[NV];
__device__ int   g_off_e[NE + 1];
__device__ int   g_off_v[NV + 1];
__device__ int   g_csr_e_v[NM];
__device__ int   g_csr_v_e[NM];
__device__ int   g_bsum_e[40];
__device__ int   g_bsum_v[40];

// ---------------- helpers ----------------
__device__ __forceinline__ uint32_t smem_u32(const void* p) {
    uint32_t a;
    asm("{ .reg .u64 t; cvta.to.shared.u64 t, %1; cvt.u32.u64 %0, t; }" : "=r"(a) : "l"(p));
    return a;
}
__device__ __forceinline__ void ldm_x4(uint32_t* r, uint32_t addr) {
    asm volatile("ldmatrix.sync.aligned.m8n8.x4.shared.b16 {%0,%1,%2,%3}, [%4];"
                 : "=r"(r[0]), "=r"(r[1]), "=r"(r[2]), "=r"(r[3]) : "r"(addr));
}
__device__ __forceinline__ void mma16816(float* d, const uint32_t* a, const uint32_t* b) {
    asm volatile(
        "mma.sync.aligned.m16n8k16.row.col.f32.bf16.bf16.f32 "
        "{%0,%1,%2,%3}, {%4,%5,%6,%7}, {%8,%9}, {%0,%1,%2,%3};"
        : "+f"(d[0]), "+f"(d[1]), "+f"(d[2]), "+f"(d[3])
        : "r"(a[0]), "r"(a[1]), "r"(a[2]), "r"(a[3]), "r"(b[0]), "r"(b[1]));
}
__device__ __forceinline__ void cp16(uint32_t saddr, const void* g, bool pred) {
    int sz = pred ? 16 : 0;
    asm volatile("cp.async.cg.shared.global [%0], [%1], 16, %2;"
                 :: "r"(saddr), "l"(g), "r"(sz) : "memory");
}
__device__ __forceinline__ void cp_commit() {
    asm volatile("cp.async.commit_group;" ::: "memory");
}
template <int N>
__device__ __forceinline__ void cp_wait() {
    asm volatile("cp.async.wait_group %0;" :: "n"(N) : "memory");
}

// ---------------- zeroing ----------------
__global__ void k_zero(float* p, long n) {
    long stride = (long)gridDim.x * blockDim.x;
    for (long i = (long)blockIdx.x * blockDim.x + threadIdx.x; i < n; i += stride)
        p[i] = 0.0f;
}
__global__ void k_zero_misc() {
    int i = blockIdx.x * blockDim.x + threadIdx.x;
    if (i < 2 * DD) g_stats[i] = 0.0f;
    if (i < NE) { g_deg_e[i] = 0; g_cur_e[i] = 0; }
    if (i < NV) { g_deg_v[i] = 0; g_cur_v[i] = 0; }
}

// ---------------- degree counting ----------------
__global__ void k_deg(const int* __restrict__ v_idx, const int* __restrict__ e_idx) {
    int i = blockIdx.x * blockDim.x + threadIdx.x;
    if (i < NM) {
        atomicAdd(&g_deg_v[v_idx[i]], 1);
        atomicAdd(&g_deg_e[e_idx[i]], 1);
    }
}

// ---------------- multi-block exclusive scan (both arrays in one grid) ----------------
#define SCHUNK 2048
#define NB_E ((NE + SCHUNK - 1) / SCHUNK)   // 5
#define NB_V ((NV + SCHUNK - 1) / SCHUNK)   // 25
__global__ void k_scan_part() {
    int b = blockIdx.x;
    const int mode = (b >= NB_E);
    const int cb = mode ? (b - NB_E) : b;
    const int* __restrict__ deg = mode ? g_deg_v : g_deg_e;
    const int n = mode ? NV : NE;
    int start = cb * SCHUNK;
    int end = min(start + SCHUNK, n);
    int s = 0;
    for (int i = start + threadIdx.x; i < end; i += 256) s += deg[i];
#pragma unroll
    for (int d = 16; d; d >>= 1) s += __shfl_down_sync(0xFFFFFFFFu, s, d);
    __shared__ int ws[8];
    if ((threadIdx.x & 31) == 0) ws[threadIdx.x >> 5] = s;
    __syncthreads();
    if (threadIdx.x == 0) {
        int t = 0;
#pragma unroll
        for (int w = 0; w < 8; w++) t += ws[w];
        if (mode) g_bsum_v[cb] = t; else g_bsum_e[cb] = t;
    }
}
__global__ void k_scan_mid() {
    if (threadIdx.x == 0) {
        int run = 0;
        for (int i = 0; i < NB_E; i++) { int t = g_bsum_e[i]; g_bsum_e[i] = run; run += t; }
    } else if (threadIdx.x == 1) {
        int run = 0;
        for (int i = 0; i < NB_V; i++) { int t = g_bsum_v[i]; g_bsum_v[i] = run; run += t; }
    }
}
__global__ void k_scan_final() {
    int b = blockIdx.x;
    const int mode = (b >= NB_E);
    const int cb = mode ? (b - NB_E) : b;
    const int* __restrict__ deg = mode ? g_deg_v : g_deg_e;
    int* __restrict__ off       = mode ? g_off_v : g_off_e;
    const int n = mode ? NV : NE;
    const int tid  = threadIdx.x;
    const int lane = tid & 31;
    const int w    = tid >> 5;
    int start = cb * SCHUNK;
    int carry = mode ? g_bsum_v[cb] : g_bsum_e[cb];
    __shared__ int ws[8];
    __shared__ int btotal;
    for (int batch = 0; batch < SCHUNK / 256; batch++) {
        int i = start + batch * 256 + tid;
        int v = (i < n) ? deg[i] : 0;
        int s = v;
#pragma unroll
        for (int d = 1; d < 32; d <<= 1) {
            int t = __shfl_up_sync(0xFFFFFFFFu, s, d);
            if (lane >= d) s += t;
        }
        if (lane == 31) ws[w] = s;
        __syncthreads();
        if (tid == 0) {
            int run = 0;
#pragma unroll
            for (int j = 0; j < 8; j++) { int t = ws[j]; ws[j] = run; run += t; }
            btotal = run;
        }
        __syncthreads();
        s += ws[w];
        if (i < n) off[i] = carry + s - v;
        if (i == n - 1) off[n] = carry + s;
        carry += btotal;
        __syncthreads();
    }
}

// ---------------- CSR fill ----------------
__global__ void k_fill(const int* __restrict__ v_idx, const int* __restrict__ e_idx) {
    int i = blockIdx.x * blockDim.x + threadIdx.x;
    if (i < NM) {
        int v = v_idx[i];
        int e = e_idx[i];
        int pe = atomicAdd(&g_cur_e[e], 1);
        g_csr_e_v[g_off_e[e] + pe] = v;
        int pv = atomicAdd(&g_cur_v[v], 1);
        g_csr_v_e[g_off_v[v] + pv] = e;
    }
}

// ---------------- split X into bf16 hi/lo ----------------
__global__ void k_splitX(const float* __restrict__ X) {
    long n4 = (long)NV * DD / 4;
    long stride = (long)gridDim.x * blockDim.x;
    for (long i4 = (long)blockIdx.x * blockDim.x + threadIdx.x; i4 < n4; i4 += stride) {
        float4 v = ((const float4*)X)[i4];
        __nv_bfloat16 h0 = __float2bfloat16(v.x);
        __nv_bfloat16 h1 = __float2bfloat16(v.y);
        __nv_bfloat16 h2 = __float2bfloat16(v.z);
        __nv_bfloat16 h3 = __float2bfloat16(v.w);
        __nv_bfloat16 l0 = __float2bfloat16(v.x - __bfloat162float(h0));
        __nv_bfloat16 l1 = __float2bfloat16(v.y - __bfloat162float(h1));
        __nv_bfloat16 l2 = __float2bfloat16(v.z - __bfloat162float(h2));
        __nv_bfloat16 l3 = __float2bfloat16(v.w - __bfloat162float(h3));
        __nv_bfloat162 hh01; hh01.x = h0; hh01.y = h1;
        __nv_bfloat162 hh23; hh23.x = h2; hh23.y = h3;
        __nv_bfloat162 ll01; ll01.x = l0; ll01.y = l1;
        __nv_bfloat162 ll23; ll23.x = l2; ll23.y = l3;
        ((__nv_bfloat162*)g_Xh)[i4 * 2 + 0] = hh01;
        ((__nv_bfloat162*)g_Xh)[i4 * 2 + 1] = hh23;
        ((__nv_bfloat162*)g_Xl)[i4 * 2 + 0] = ll01;
        ((__nv_bfloat162*)g_Xl)[i4 * 2 + 1] = ll23;
    }
}

// ---------------- split + transpose W ----------------
__global__ void k_splitW(const float* __restrict__ W) {
    int i = blockIdx.x * blockDim.x + threadIdx.x;  // i = n*512 + k
    if (i < DD * DD) {
        int n = i >> 9, k = i & 511;
        float v = W[(size_t)k * DD + n];
        __nv_bfloat16 h = __float2bfloat16(v);
        __nv_bfloat16 l = __float2bfloat16(v - __bfloat162float(h));
        g_Wth[i] = h;
        g_Wtl[i] = l;
    }
}

// ---------------- mma.sync GEMM: block 128(M)x256(N), warp tile 64x64 ----------------
#define SPAD 40
#define A_BUF (128 * SPAD * 2)              // bytes per A buffer
#define B_BUF (256 * SPAD * 2)              // bytes per B buffer
#define GT_SMEM (2 * A_BUF + 2 * B_BUF)     // 61440
__global__ __launch_bounds__(256, 1) void k_gemm_mma(const float* __restrict__ bias) {
    extern __shared__ __align__(16) char dsm[];
    const uint32_t sb = smem_u32(dsm);
    const uint32_t aoff[2] = {sb, sb + A_BUF};
    const uint32_t boff[2] = {sb + 2 * A_BUF, sb + 2 * A_BUF + B_BUF};

    const int tid    = threadIdx.x;
    const int wid    = tid >> 5;
    const int lane   = tid & 31;
    const int warp_m = wid & 1;    // 0..1
    const int warp_n = wid >> 1;   // 0..3
    const int row0   = blockIdx.y * 128;
    const int n0     = blockIdx.x * 256;

    // cp.async coordinates
    const int ld_r = tid >> 2;            // 0..63
    const int ld_q = (tid & 3) * 8;       // bf16 col within 32

    // ldmatrix lane addressing (element offsets)
    const int a_row = warp_m * 64 + (lane & 15);
    const int a_col = ((lane >> 4) << 3);
    const int b_row = warp_n * 64 + ((lane >> 4) << 3) + (lane & 7);
    const int b_col = ((lane >> 3) & 1) << 3;

    float acc[4][8][4];
#pragma unroll
    for (int i = 0; i < 4; i++)
#pragma unroll
        for (int j = 0; j < 8; j++)
#pragma unroll
            for (int r = 0; r < 4; r++) acc[i][j][r] = 0.0f;

    auto issue_tile = [&](int kg, int buf) {
        const int seg = kg >> 4;
        const int k0  = (kg & 15) * 32;
        const __nv_bfloat16* Ap = (seg < 2) ? g_Xh : g_Xl;
        const __nv_bfloat16* Bp = (seg == 1) ? g_Wtl : g_Wth;
        // A: 128 rows, 2 uint4/thread
#pragma unroll
        for (int i = 0; i < 2; i++) {
            int r = ld_r + i * 64;
            int gr = row0 + r;
            bool ok = gr < NV;
            int grc = ok ? gr : 0;
            cp16(aoff[buf] + (r * SPAD + ld_q) * 2, Ap + (size_t)grc * DD + k0 + ld_q, ok);
        }
        // B: 256 rows, 4 uint4/thread
#pragma unroll
        for (int i = 0; i < 4; i++) {
            int r = ld_r + i * 64;
            cp16(boff[buf] + (r * SPAD + ld_q) * 2, Bp + (size_t)(n0 + r) * DD + k0 + ld_q, true);
        }
        cp_commit();
    };

    issue_tile(0, 0);
#pragma unroll 1
    for (int kg = 0; kg < 48; kg++) {
        const int buf = kg & 1;
        if (kg + 1 < 48) {
            issue_tile(kg + 1, buf ^ 1);
            cp_wait<1>();
        } else {
            cp_wait<0>();
        }
        __syncthreads();

        const uint32_t ab = aoff[buf];
        const uint32_t bb = boff[buf];
#pragma unroll
        for (int k16 = 0; k16 < 2; k16++) {
            const int kk = k16 * 16;
            uint32_t a[4][4];
#pragma unroll
            for (int mt = 0; mt < 4; mt++)
                ldm_x4(a[mt], ab + ((a_row + mt * 16) * SPAD + a_col + kk) * 2);
            uint32_t bf[4][4];
#pragma unroll
            for (int np = 0; np < 4; np++)
                ldm_x4(bf[np], bb + ((b_row + np * 16) * SPAD + b_col + kk) * 2);
#pragma unroll
            for (int mt = 0; mt < 4; mt++)
#pragma unroll
                for (int nt = 0; nt < 8; nt++)
                    mma16816(acc[mt][nt], a[mt], &bf[nt >> 1][(nt & 1) * 2]);
        }
        __syncthreads();
    }

    // epilogue: D frag -> g_Y (+bias)
    const int mrow = lane >> 2;
    const int mcol = (lane & 3) * 2;
#pragma unroll
    for (int mt = 0; mt < 4; mt++) {
#pragma unroll
        for (int nt = 0; nt < 8; nt++) {
            int gc = n0 + warp_n * 64 + nt * 8 + mcol;
            float2 bb2 = *(const float2*)(bias + gc);
            int gr0 = row0 + warp_m * 64 + mt * 16 + mrow;
            if (gr0 < NV) {
                float2 o = make_float2(acc[mt][nt][0] + bb2.x, acc[mt][nt][1] + bb2.y);
                *(float2*)(g_Y + (size_t)gr0 * DD + gc) = o;
            }
            int gr1 = gr0 + 8;
            if (gr1 < NV) {
                float2 o = make_float2(acc[mt][nt][2] + bb2.x, acc[mt][nt][3] + bb2.y);
                *(float2*)(g_Y + (size_t)gr1 * DD + gc) = o;
            }
        }
    }
}

// ---------------- per-column BN stats over g_Y ----------------
__global__ void k_colstats() {
    int c = threadIdx.x;
    float s = 0.0f, s2 = 0.0f;
    for (int r = blockIdx.x; r < NV; r += gridDim.x) {
        float v = g_Y[(size_t)r * DD + c];
        s += v;
        s2 += v * v;
    }
    atomicAdd(&g_stats[c], s);
    atomicAdd(&g_stats[DD + c], s2);
}

__global__ void k_finalize(const float* __restrict__ gamma, const float* __restrict__ beta) {
    int c = threadIdx.x;
    float mu  = g_stats[c] * (1.0f / NV);
    float var = g_stats[DD + c] * (1.0f / NV) - mu * mu;
    float rs  = rsqrtf(var + BN_EPS);
    float sc  = gamma[c] * rs;
    g_scale[c] = sc;
    g_shift[c] = beta[c] - mu * sc;
}

// ---------------- v2e (CSR gather) ----------------
__global__ __launch_bounds__(128) void k_v2e(float* __restrict__ HE) {
    int e  = blockIdx.x;
    int c4 = threadIdx.x * 4;
    int s = g_off_e[e], t = g_off_e[e + 1];
    float4 acc = make_float4(0.f, 0.f, 0.f, 0.f);
    int j = s;
    for (; j + 4 <= t; j += 4) {
        int v0 = g_csr_e_v[j + 0];
        int v1 = g_csr_e_v[j + 1];
        int v2 = g_csr_e_v[j + 2];
        int v3 = g_csr_e_v[j + 3];
        float4 y0 = *(const float4*)(g_Y + (size_t)v0 * DD + c4);
        float4 y1 = *(const float4*)(g_Y + (size_t)v1 * DD + c4);
        float4 y2 = *(const float4*)(g_Y + (size_t)v2 * DD + c4);
        float4 y3 = *(const float4*)(g_Y + (size_t)v3 * DD + c4);
        acc.x += (y0.x + y1.x) + (y2.x + y3.x);
        acc.y += (y0.y + y1.y) + (y2.y + y3.y);
        acc.z += (y0.z + y1.z) + (y2.z + y3.z);
        acc.w += (y0.w + y1.w) + (y2.w + y3.w);
    }
    for (; j < t; j++) {
        int v = g_csr_e_v[j];
        float4 y = *(const float4*)(g_Y + (size_t)v * DD + c4);
        acc.x += y.x; acc.y += y.y; acc.z += y.z; acc.w += y.w;
    }
    float w = 1.0f / (float)max(t - s, 1);
    float4 sc = *(const float4*)(g_scale + c4);
    float4 sh = *(const float4*)(g_shift + c4);
    float4 o;
    o.x = fmaf(acc.x * w, sc.x, sh.x);
    o.y = fmaf(acc.y * w, sc.y, sh.y);
    o.z = fmaf(acc.z * w, sc.z, sh.z);
    o.w = fmaf(acc.w * w, sc.w, sh.w);
    *(float4*)(HE + (size_t)e * DD + c4) = o;
}

// ---------------- e2v (CSR gather) ----------------
__global__ __launch_bounds__(128) void k_e2v(const float* __restrict__ HE,
                                             float* __restrict__ Xout) {
    int v  = blockIdx.x;
    int c4 = threadIdx.x * 4;
    int s = g_off_v[v], t = g_off_v[v + 1];
    float4 acc = make_float4(0.f, 0.f, 0.f, 0.f);
    int j = s;
    for (; j + 4 <= t; j += 4) {
        int e0 = g_csr_v_e[j + 0];
        int e1 = g_csr_v_e[j + 1];
        int e2 = g_csr_v_e[j + 2];
        int e3 = g_csr_v_e[j + 3];
        float4 h0 = *(const float4*)(HE + (size_t)e0 * DD + c4);
        float4 h1 = *(const float4*)(HE + (size_t)e1 * DD + c4);
        float4 h2 = *(const float4*)(HE + (size_t)e2 * DD + c4);
        float4 h3 = *(const float4*)(HE + (size_t)e3 * DD + c4);
        acc.x += (h0.x + h1.x) + (h2.x + h3.x);
        acc.y += (h0.y + h1.y) + (h2.y + h3.y);
        acc.z += (h0.z + h1.z) + (h2.z + h3.z);
        acc.w += (h0.w + h1.w) + (h2.w + h3.w);
    }
    for (; j < t; j++) {
        int e = g_csr_v_e[j];
        float4 h = *(const float4*)(HE + (size_t)e * DD + c4);
        acc.x += h.x; acc.y += h.y; acc.z += h.z; acc.w += h.w;
    }
    float w = 1.0f / (float)max(t - s, 1);
    float4 o = make_float4(acc.x * w, acc.y * w, acc.z * w, acc.w * w);
    *(float4*)(Xout + (size_t)v * DD + c4) = o;
}

// ---------------- launcher ----------------
extern "C" void kernel_launch(void* const* d_in, const int* in_sizes, int n_in,
                              void* d_out, int out_size) {
    const float* X     = (const float*)d_in[0];
    const float* W     = (const float*)d_in[1];
    const float* b     = (const float*)d_in[2];
    const float* gamma = (const float*)d_in[3];
    const float* beta  = (const float*)d_in[4];
    const int* v_idx   = (const int*)d_in[5];
    const int* e_idx   = (const int*)d_in[6];

    float* Xout = (float*)d_out;
    float* HE   = Xout + (size_t)NV * DD;

    cudaFuncSetAttribute(k_gemm_mma, cudaFuncAttributeMaxDynamicSharedMemorySize, GT_SMEM);

    k_zero_misc<<<(NV + 255) / 256, 256>>>();
    long expected = (long)(NV + NE) * DD;
    if ((long)out_size > expected)
        k_zero<<<64, 256>>>(Xout + expected, (long)out_size - expected);

    // CSR build (e and v scans fused per launch)
    k_deg<<<(NM + 255) / 256, 256>>>(v_idx, e_idx);
    k_scan_part<<<NB_E + NB_V, 256>>>();
    k_scan_mid<<<1, 32>>>();
    k_scan_final<<<NB_E + NB_V, 256>>>();
    k_fill<<<(NM + 255) / 256, 256>>>(v_idx, e_idx);

    // split inputs to bf16 hi/lo
    k_splitX<<<2048, 256>>>(X);
    k_splitW<<<(DD * DD + 255) / 256, 256>>>(W);

    // tensor-core (mma.sync) GEMM  Y = X @ W + b
    dim3 gg(DD / 256, (NV + 127) / 128);
    k_gemm_mma<<<gg, 256, GT_SMEM>>>(b);

    // BN stats folded into per-column scale/shift
    k_colstats<<<512, DD>>>();
    k_finalize<<<1, DD>>>(gamma, beta);

    // gather-based segment means
    k_v2e<<<NE, 128>>>(HE);
    k_e2v<<<NV, 128>>>(HE, Xout);
}

// round 8
// speedup vs baseline: 1.7717x; 1.7717x over previous
#include <cuda_runtime.h>
#include <cuda_fp16.h>
#include <cstdint>

#define NV 50000
#define NE 10000
#define NM 200000
#define DD 512
#define BN_EPS 1e-5f

// ---------------- scratch (static device globals; no allocation) ----------------
__device__ float g_Y[(size_t)NV * DD];     // GEMM output (pre-BN)
__device__ __half g_Xh[(size_t)NV * DD];   // X in fp16
__device__ __half g_Wth[DD * DD];          // W^T hi fp16   [n][k]
__device__ __half g_Wtl[DD * DD];          // W^T residual  [n][k]
__device__ float g_stats[2 * DD];
__device__ float g_scale[DD];
__device__ float g_shift[DD];
__device__ int   g_deg_e[NE];
__device__ int   g_deg_v[NV];
__device__ int   g_cur_e[NE];
__device__ int   g_cur_v[NV];
__device__ int   g_off_e[NE + 1];
__device__ int   g_off_v[NV + 1];
__device__ int   g_csr_e_v[NM];
__device__ int   g_csr_v_e[NM];
__device__ int   g_bsum_e[40];
__device__ int   g_bsum_v[40];

// ---------------- helpers ----------------
__device__ __forceinline__ uint32_t smem_u32(const void* p) {
    uint32_t a;
    asm("{ .reg .u64 t; cvta.to.shared.u64 t, %1; cvt.u32.u64 %0, t; }" : "=r"(a) : "l"(p));
    return a;
}
__device__ __forceinline__ void ldm_x4(uint32_t* r, uint32_t addr) {
    asm volatile("ldmatrix.sync.aligned.m8n8.x4.shared.b16 {%0,%1,%2,%3}, [%4];"
                 : "=r"(r[0]), "=r"(r[1]), "=r"(r[2]), "=r"(r[3]) : "r"(addr));
}
__device__ __forceinline__ void mma16816(float* d, const uint32_t* a, const uint32_t* b) {
    asm volatile(
        "mma.sync.aligned.m16n8k16.row.col.f32.f16.f16.f32 "
        "{%0,%1,%2,%3}, {%4,%5,%6,%7}, {%8,%9}, {%0,%1,%2,%3};"
        : "+f"(d[0]), "+f"(d[1]), "+f"(d[2]), "+f"(d[3])
        : "r"(a[0]), "r"(a[1]), "r"(a[2]), "r"(a[3]), "r"(b[0]), "r"(b[1]));
}
__device__ __forceinline__ void cp16(uint32_t saddr, const void* g, bool pred) {
    int sz = pred ? 16 : 0;
    asm volatile("cp.async.cg.shared.global [%0], [%1], 16, %2;"
                 :: "r"(saddr), "l"(g), "r"(sz) : "memory");
}
__device__ __forceinline__ void cp_commit() {
    asm volatile("cp.async.commit_group;" ::: "memory");
}
template <int N>
__device__ __forceinline__ void cp_wait() {
    asm volatile("cp.async.wait_group %0;" :: "n"(N) : "memory");
}

// ---------------- zeroing ----------------
__global__ void k_zero(float* p, long n) {
    long stride = (long)gridDim.x * blockDim.x;
    for (long i = (long)blockIdx.x * blockDim.x + threadIdx.x; i < n; i += stride)
        p[i] = 0.0f;
}
__global__ void k_zero_misc() {
    int i = blockIdx.x * blockDim.x + threadIdx.x;
    if (i < 2 * DD) g_stats[i] = 0.0f;
    if (i < NE) { g_deg_e[i] = 0; g_cur_e[i] = 0; }
    if (i < NV) { g_deg_v[i] = 0; g_cur_v[i] = 0; }
}

// ---------------- degree counting ----------------
__global__ void k_deg(const int* __restrict__ v_idx, const int* __restrict__ e_idx) {
    int i = blockIdx.x * blockDim.x + threadIdx.x;
    if (i < NM) {
        atomicAdd(&g_deg_v[v_idx[i]], 1);
        atomicAdd(&g_deg_e[e_idx[i]], 1);
    }
}

// ---------------- multi-block exclusive scan (both arrays in one grid) ----------------
#define SCHUNK 2048
#define NB_E ((NE + SCHUNK - 1) / SCHUNK)   // 5
#define NB_V ((NV + SCHUNK - 1) / SCHUNK)   // 25
__global__ void k_scan_part() {
    int b = blockIdx.x;
    const int mode = (b >= NB_E);
    const int cb = mode ? (b - NB_E) : b;
    const int* __restrict__ deg = mode ? g_deg_v : g_deg_e;
    const int n = mode ? NV : NE;
    int start = cb * SCHUNK;
    int end = min(start + SCHUNK, n);
    int s = 0;
    for (int i = start + threadIdx.x; i < end; i += 256) s += deg[i];
#pragma unroll
    for (int d = 16; d; d >>= 1) s += __shfl_down_sync(0xFFFFFFFFu, s, d);
    __shared__ int ws[8];
    if ((threadIdx.x & 31) == 0) ws[threadIdx.x >> 5] = s;
    __syncthreads();
    if (threadIdx.x == 0) {
        int t = 0;
#pragma unroll
        for (int w = 0; w < 8; w++) t += ws[w];
        if (mode) g_bsum_v[cb] = t; else g_bsum_e[cb] = t;
    }
}
__global__ void k_scan_mid() {
    if (threadIdx.x == 0) {
        int run = 0;
        for (int i = 0; i < NB_E; i++) { int t = g_bsum_e[i]; g_bsum_e[i] = run; run += t; }
    } else if (threadIdx.x == 1) {
        int run = 0;
        for (int i = 0; i < NB_V; i++) { int t = g_bsum_v[i]; g_bsum_v[i] = run; run += t; }
    }
}
__global__ void k_scan_final() {
    int b = blockIdx.x;
    const int mode = (b >= NB_E);
    const int cb = mode ? (b - NB_E) : b;
    const int* __restrict__ deg = mode ? g_deg_v : g_deg_e;
    int* __restrict__ off       = mode ? g_off_v : g_off_e;
    const int n = mode ? NV : NE;
    const int tid  = threadIdx.x;
    const int lane = tid & 31;
    const int w    = tid >> 5;
    int start = cb * SCHUNK;
    int carry = mode ? g_bsum_v[cb] : g_bsum_e[cb];
    __shared__ int ws[8];
    __shared__ int btotal;
    for (int batch = 0; batch < SCHUNK / 256; batch++) {
        int i = start + batch * 256 + tid;
        int v = (i < n) ? deg[i] : 0;
        int s = v;
#pragma unroll
        for (int d = 1; d < 32; d <<= 1) {
            int t = __shfl_up_sync(0xFFFFFFFFu, s, d);
            if (lane >= d) s += t;
        }
        if (lane == 31) ws[w] = s;
        __syncthreads();
        if (tid == 0) {
            int run = 0;
#pragma unroll
            for (int j = 0; j < 8; j++) { int t = ws[j]; ws[j] = run; run += t; }
            btotal = run;
        }
        __syncthreads();
        s += ws[w];
        if (i < n) off[i] = carry + s - v;
        if (i == n - 1) off[n] = carry + s;
        carry += btotal;
        __syncthreads();
    }
}

// ---------------- CSR fill ----------------
__global__ void k_fill(const int* __restrict__ v_idx, const int* __restrict__ e_idx) {
    int i = blockIdx.x * blockDim.x + threadIdx.x;
    if (i < NM) {
        int v = v_idx[i];
        int e = e_idx[i];
        int pe = atomicAdd(&g_cur_e[e], 1);
        g_csr_e_v[g_off_e[e] + pe] = v;
        int pv = atomicAdd(&g_cur_v[v], 1);
        g_csr_v_e[g_off_v[v] + pv] = e;
    }
}

// ---------------- convert X to fp16 ----------------
__global__ void k_cvtX(const float* __restrict__ X) {
    long n4 = (long)NV * DD / 4;
    long stride = (long)gridDim.x * blockDim.x;
    for (long i4 = (long)blockIdx.x * blockDim.x + threadIdx.x; i4 < n4; i4 += stride) {
        float4 v = ((const float4*)X)[i4];
        __half2 h01 = __floats2half2_rn(v.x, v.y);
        __half2 h23 = __floats2half2_rn(v.z, v.w);
        ((__half2*)g_Xh)[i4 * 2 + 0] = h01;
        ((__half2*)g_Xh)[i4 * 2 + 1] = h23;
    }
}

// ---------------- split + transpose W into fp16 hi/residual ----------------
__global__ void k_splitW(const float* __restrict__ W) {
    int i = blockIdx.x * blockDim.x + threadIdx.x;  // i = n*512 + k
    if (i < DD * DD) {
        int n = i >> 9, k = i & 511;
        float v = W[(size_t)k * DD + n];
        __half h = __float2half_rn(v);
        __half l = __float2half_rn(v - __half2float(h));
        g_Wth[i] = h;
        g_Wtl[i] = l;
    }
}

// ---------------- fp16 GEMM: Y = Xh@(Wh+Wl) + b, stats fused in epilogue --------
// Block 128x128, BK=32, 8 warps (64x32 warp tiles), 2 CTAs/SM, A shared by both B mats.
#define SPAD 40
#define TBUF (128 * SPAD * 2)               // 10240 bytes per tile buffer
#define GT_SMEM (6 * TBUF)                  // A,Bh,Bl double buffered = 61440
__global__ __launch_bounds__(256, 2) void k_gemm_mma(const float* __restrict__ bias) {
    extern __shared__ __align__(16) char dsm[];
    const uint32_t sb = smem_u32(dsm);
    // layout: A0 A1 Bh0 Bh1 Bl0 Bl1
    const uint32_t aoff[2]  = {sb,            sb + TBUF};
    const uint32_t bhoff[2] = {sb + 2 * TBUF, sb + 3 * TBUF};
    const uint32_t bloff[2] = {sb + 4 * TBUF, sb + 5 * TBUF};

    const int tid    = threadIdx.x;
    const int wid    = tid >> 5;
    const int lane   = tid & 31;
    const int warp_m = wid >> 2;   // 0..1
    const int warp_n = wid & 3;    // 0..3
    const int row0   = blockIdx.y * 128;
    const int n0     = blockIdx.x * 128;

    const int ld_r = tid >> 2;            // 0..63
    const int ld_q = (tid & 3) * 8;       // fp16 col within 32

    const int a_row = warp_m * 64 + (lane & 15);
    const int a_col = ((lane >> 4) << 3);
    const int b_row = warp_n * 32 + ((lane >> 4) << 3) + (lane & 7);
    const int b_col = ((lane >> 3) & 1) << 3;

    float acc[4][4][4];
#pragma unroll
    for (int i = 0; i < 4; i++)
#pragma unroll
        for (int j = 0; j < 4; j++)
#pragma unroll
            for (int r = 0; r < 4; r++) acc[i][j][r] = 0.0f;

    auto issue_tile = [&](int kt, int buf) {
        const int k0 = kt * 32;
#pragma unroll
        for (int i = 0; i < 2; i++) {
            int r = ld_r + i * 64;
            int gr = row0 + r;
            bool ok = gr < NV;
            int grc = ok ? gr : 0;
            cp16(aoff[buf] + (r * SPAD + ld_q) * 2, g_Xh + (size_t)grc * DD + k0 + ld_q, ok);
            cp16(bhoff[buf] + (r * SPAD + ld_q) * 2, g_Wth + (size_t)(n0 + r) * DD + k0 + ld_q, true);
            cp16(bloff[buf] + (r * SPAD + ld_q) * 2, g_Wtl + (size_t)(n0 + r) * DD + k0 + ld_q, true);
        }
        cp_commit();
    };

    issue_tile(0, 0);
#pragma unroll 1
    for (int kt = 0; kt < 16; kt++) {
        const int buf = kt & 1;
        if (kt + 1 < 16) {
            issue_tile(kt + 1, buf ^ 1);
            cp_wait<1>();
        } else {
            cp_wait<0>();
        }
        __syncthreads();

#pragma unroll
        for (int k16 = 0; k16 < 2; k16++) {
            const int kk = k16 * 16;
            uint32_t a[4][4];
#pragma unroll
            for (int mt = 0; mt < 4; mt++)
                ldm_x4(a[mt], aoff[buf] + ((a_row + mt * 16) * SPAD + a_col + kk) * 2);
            uint32_t bh[2][4], bl[2][4];
#pragma unroll
            for (int np = 0; np < 2; np++) {
                ldm_x4(bh[np], bhoff[buf] + ((b_row + np * 16) * SPAD + b_col + kk) * 2);
                ldm_x4(bl[np], bloff[buf] + ((b_row + np * 16) * SPAD + b_col + kk) * 2);
            }
#pragma unroll
            for (int mt = 0; mt < 4; mt++)
#pragma unroll
                for (int nt = 0; nt < 4; nt++) {
                    mma16816(acc[mt][nt], a[mt], &bh[nt >> 1][(nt & 1) * 2]);
                    mma16816(acc[mt][nt], a[mt], &bl[nt >> 1][(nt & 1) * 2]);
                }
        }
        __syncthreads();
    }

    // ---- epilogue: bias add, store Y, fused per-column stats ----
    const int mrow = lane >> 2;
    const int mcol = (lane & 3) * 2;
    float cs[4][2], cq[4][2];
#pragma unroll
    for (int nt = 0; nt < 4; nt++) {
        cs[nt][0] = cs[nt][1] = 0.0f;
        cq[nt][0] = cq[nt][1] = 0.0f;
    }
#pragma unroll
    for (int mt = 0; mt < 4; mt++) {
        int gr0 = row0 + warp_m * 64 + mt * 16 + mrow;
        int gr1 = gr0 + 8;
        bool ok0 = gr0 < NV, ok1 = gr1 < NV;
#pragma unroll
        for (int nt = 0; nt < 4; nt++) {
            int gc = n0 + warp_n * 32 + nt * 8 + mcol;
            float2 bb = *(const float2*)(bias + gc);
            if (ok0) {
                float ox = acc[mt][nt][0] + bb.x;
                float oy = acc[mt][nt][1] + bb.y;
                *(float2*)(g_Y + (size_t)gr0 * DD + gc) = make_float2(ox, oy);
                cs[nt][0] += ox; cq[nt][0] += ox * ox;
                cs[nt][1] += oy; cq[nt][1] += oy * oy;
            }
            if (ok1) {
                float ox = acc[mt][nt][2] + bb.x;
                float oy = acc[mt][nt][3] + bb.y;
                *(float2*)(g_Y + (size_t)gr1 * DD + gc) = make_float2(ox, oy);
                cs[nt][0] += ox; cq[nt][0] += ox * ox;
                cs[nt][1] += oy; cq[nt][1] += oy * oy;
            }
        }
    }
    // reduce across lanes with same (lane&3): strides 16, 8, 4
#pragma unroll
    for (int off = 16; off >= 4; off >>= 1) {
#pragma unroll
        for (int nt = 0; nt < 4; nt++) {
#pragma unroll
            for (int j = 0; j < 2; j++) {
                cs[nt][j] += __shfl_down_sync(0xFFFFFFFFu, cs[nt][j], off);
                cq[nt][j] += __shfl_down_sync(0xFFFFFFFFu, cq[nt][j], off);
            }
        }
    }
    if (lane < 4) {
#pragma unroll
        for (int nt = 0; nt < 4; nt++) {
#pragma unroll
            for (int j = 0; j < 2; j++) {
                int gc = n0 + warp_n * 32 + nt * 8 + lane * 2 + j;
                atomicAdd(&g_stats[gc], cs[nt][j]);
                atomicAdd(&g_stats[DD + gc], cq[nt][j]);
            }
        }
    }
}

// ---------------- finalize BN scale/shift ----------------
__global__ void k_finalize(const float* __restrict__ gamma, const float* __restrict__ beta) {
    int c = threadIdx.x;
    float mu  = g_stats[c] * (1.0f / NV);
    float var = g_stats[DD + c] * (1.0f / NV) - mu * mu;
    float rs  = rsqrtf(var + BN_EPS);
    float sc  = gamma[c] * rs;
    g_scale[c] = sc;
    g_shift[c] = beta[c] - mu * sc;
}

// ---------------- v2e (CSR gather) ----------------
__global__ __launch_bounds__(128) void k_v2e(float* __restrict__ HE) {
    int e  = blockIdx.x;
    int c4 = threadIdx.x * 4;
    int s = g_off_e[e], t = g_off_e[e + 1];
    float4 acc = make_float4(0.f, 0.f, 0.f, 0.f);
    int j = s;
    for (; j + 4 <= t; j += 4) {
        int v0 = g_csr_e_v[j + 0];
        int v1 = g_csr_e_v[j + 1];
        int v2 = g_csr_e_v[j + 2];
        int v3 = g_csr_e_v[j + 3];
        float4 y0 = *(const float4*)(g_Y + (size_t)v0 * DD + c4);
        float4 y1 = *(const float4*)(g_Y + (size_t)v1 * DD + c4);
        float4 y2 = *(const float4*)(g_Y + (size_t)v2 * DD + c4);
        float4 y3 = *(const float4*)(g_Y + (size_t)v3 * DD + c4);
        acc.x += (y0.x + y1.x) + (y2.x + y3.x);
        acc.y += (y0.y + y1.y) + (y2.y + y3.y);
        acc.z += (y0.z + y1.z) + (y2.z + y3.z);
        acc.w += (y0.w + y1.w) + (y2.w + y3.w);
    }
    for (; j < t; j++) {
        int v = g_csr_e_v[j];
        float4 y = *(const float4*)(g_Y + (size_t)v * DD + c4);
        acc.x += y.x; acc.y += y.y; acc.z += y.z; acc.w += y.w;
    }
    float w = 1.0f / (float)max(t - s, 1);
    float4 sc = *(const float4*)(g_scale + c4);
    float4 sh = *(const float4*)(g_shift + c4);
    float4 o;
    o.x = fmaf(acc.x * w, sc.x, sh.x);
    o.y = fmaf(acc.y * w, sc.y, sh.y);
    o.z = fmaf(acc.z * w, sc.z, sh.z);
    o.w = fmaf(acc.w * w, sc.w, sh.w);
    *(float4*)(HE + (size_t)e * DD + c4) = o;
}

// ---------------- e2v (CSR gather) ----------------
__global__ __launch_bounds__(128) void k_e2v(const float* __restrict__ HE,
                                             float* __restrict__ Xout) {
    int v  = blockIdx.x;
    int c4 = threadIdx.x * 4;
    int s = g_off_v[v], t = g_off_v[v + 1];
    float4 acc = make_float4(0.f, 0.f, 0.f, 0.f);
    int j = s;
    for (; j + 4 <= t; j += 4) {
        int e0 = g_csr_v_e[j + 0];
        int e1 = g_csr_v_e[j + 1];
        int e2 = g_csr_v_e[j + 2];
        int e3 = g_csr_v_e[j + 3];
        float4 h0 = *(const float4*)(HE + (size_t)e0 * DD + c4);
        float4 h1 = *(const float4*)(HE + (size_t)e1 * DD + c4);
        float4 h2 = *(const float4*)(HE + (size_t)e2 * DD + c4);
        float4 h3 = *(const float4*)(HE + (size_t)e3 * DD + c4);
        acc.x += (h0.x + h1.x) + (h2.x + h3.x);
        acc.y += (h0.y + h1.y) + (h2.y + h3.y);
        acc.z += (h0.z + h1.z) + (h2.z + h3.z);
        acc.w += (h0.w + h1.w) + (h2.w + h3.w);
    }
    for (; j < t; j++) {
        int e = g_csr_v_e[j];
        float4 h = *(const float4*)(HE + (size_t)e * DD + c4);
        acc.x += h.x; acc.y += h.y; acc.z += h.z; acc.w += h.w;
    }
    float w = 1.0f / (float)max(t - s, 1);
    float4 o = make_float4(acc.x * w, acc.y * w, acc.z * w, acc.w * w);
    *(float4*)(Xout + (size_t)v * DD + c4) = o;
}

// ---------------- launcher ----------------
extern "C" void kernel_launch(void* const* d_in, const int* in_sizes, int n_in,
                              void* d_out, int out_size) {
    const float* X     = (const float*)d_in[0];
    const float* W     = (const float*)d_in[1];
    const float* b     = (const float*)d_in[2];
    const float* gamma = (const float*)d_in[3];
    const float* beta  = (const float*)d_in[4];
    const int* v_idx   = (const int*)d_in[5];
    const int* e_idx   = (const int*)d_in[6];

    float* Xout = (float*)d_out;
    float* HE   = Xout + (size_t)NV * DD;

    cudaFuncSetAttribute(k_gemm_mma, cudaFuncAttributeMaxDynamicSharedMemorySize, GT_SMEM);

    k_zero_misc<<<(NV + 255) / 256, 256>>>();
    long expected = (long)(NV + NE) * DD;
    if ((long)out_size > expected)
        k_zero<<<64, 256>>>(Xout + expected, (long)out_size - expected);

    // CSR build
    k_deg<<<(NM + 255) / 256, 256>>>(v_idx, e_idx);
    k_scan_part<<<NB_E + NB_V, 256>>>();
    k_scan_mid<<<1, 32>>>();
    k_scan_final<<<NB_E + NB_V, 256>>>();
    k_fill<<<(NM + 255) / 256, 256>>>(v_idx, e_idx);

    // precision prep
    k_cvtX<<<2048, 256>>>(X);
    k_splitW<<<(DD * DD + 255) / 256, 256>>>(W);

    // fp16 tensor-core GEMM with fused BN stats
    dim3 gg(DD / 128, (NV + 127) / 128);
    k_gemm_mma<<<gg, 256, GT_SMEM>>>(b);
    k_finalize<<<1, DD>>>(gamma, beta);

    // gather-based segment means
    k_v2e<<<NE, 128>>>(HE);
    k_e2v<<<NV, 128>>>(HE, Xout);
}

// round 9
// speedup vs baseline: 2.3150x; 1.3066x over previous
#include <cuda_runtime.h>
#include <cuda_fp16.h>
#include <cstdint>

#define NV 50000
#define NE 10000
#define NM 200000
#define DD 512
#define BN_EPS 1e-5f

// ---------------- scratch (static device globals; no allocation) ----------------
__device__ __half g_Yh[(size_t)NV * DD];   // GEMM output (pre-BN) in fp16, 51.2 MB
__device__ __half g_Xh[(size_t)NV * DD];   // X in fp16
__device__ __half g_Wth[DD * DD];          // W^T fp16   [n][k]
__device__ __half g_HEh[(size_t)NE * DD];  // HE shadow in fp16
__device__ float g_stats[2 * DD];
__device__ float g_scale[DD];
__device__ float g_shift[DD];
__device__ int   g_deg_e[NE];
__device__ int   g_deg_v[NV];
__device__ int   g_cur_e[NE];
__device__ int   g_cur_v[NV];
__device__ int   g_off_e[NE + 1];
__device__ int   g_off_v[NV + 1];
__device__ int   g_csr_e_v[NM];
__device__ int   g_csr_v_e[NM];
__device__ int   g_bsum_e[40];
__device__ int   g_bsum_v[40];

// ---------------- helpers ----------------
__device__ __forceinline__ uint32_t smem_u32(const void* p) {
    uint32_t a;
    asm("{ .reg .u64 t; cvta.to.shared.u64 t, %1; cvt.u32.u64 %0, t; }" : "=r"(a) : "l"(p));
    return a;
}
__device__ __forceinline__ void ldm_x4(uint32_t* r, uint32_t addr) {
    asm volatile("ldmatrix.sync.aligned.m8n8.x4.shared.b16 {%0,%1,%2,%3}, [%4];"
                 : "=r"(r[0]), "=r"(r[1]), "=r"(r[2]), "=r"(r[3]) : "r"(addr));
}
__device__ __forceinline__ void mma16816(float* d, const uint32_t* a, const uint32_t* b) {
    asm volatile(
        "mma.sync.aligned.m16n8k16.row.col.f32.f16.f16.f32 "
        "{%0,%1,%2,%3}, {%4,%5,%6,%7}, {%8,%9}, {%0,%1,%2,%3};"
        : "+f"(d[0]), "+f"(d[1]), "+f"(d[2]), "+f"(d[3])
        : "r"(a[0]), "r"(a[1]), "r"(a[2]), "r"(a[3]), "r"(b[0]), "r"(b[1]));
}
__device__ __forceinline__ void cp16(uint32_t saddr, const void* g, bool pred) {
    int sz = pred ? 16 : 0;
    asm volatile("cp.async.cg.shared.global [%0], [%1], 16, %2;"
                 :: "r"(saddr), "l"(g), "r"(sz) : "memory");
}
__device__ __forceinline__ void cp_commit() {
    asm volatile("cp.async.commit_group;" ::: "memory");
}
template <int N>
__device__ __forceinline__ void cp_wait() {
    asm volatile("cp.async.wait_group %0;" :: "n"(N) : "memory");
}

// ---------------- zeroing ----------------
__global__ void k_zero(float* p, long n) {
    long stride = (long)gridDim.x * blockDim.x;
    for (long i = (long)blockIdx.x * blockDim.x + threadIdx.x; i < n; i += stride)
        p[i] = 0.0f;
}
__global__ void k_zero_misc() {
    int i = blockIdx.x * blockDim.x + threadIdx.x;
    if (i < 2 * DD) g_stats[i] = 0.0f;
    if (i < NE) { g_deg_e[i] = 0; g_cur_e[i] = 0; }
    if (i < NV) { g_deg_v[i] = 0; g_cur_v[i] = 0; }
}

// ---------------- degree counting ----------------
__global__ void k_deg(const int* __restrict__ v_idx, const int* __restrict__ e_idx) {
    int i = blockIdx.x * blockDim.x + threadIdx.x;
    if (i < NM) {
        atomicAdd(&g_deg_v[v_idx[i]], 1);
        atomicAdd(&g_deg_e[e_idx[i]], 1);
    }
}

// ---------------- multi-block exclusive scan (both arrays in one grid) ----------------
#define SCHUNK 2048
#define NB_E ((NE + SCHUNK - 1) / SCHUNK)   // 5
#define NB_V ((NV + SCHUNK - 1) / SCHUNK)   // 25
__global__ void k_scan_part() {
    int b = blockIdx.x;
    const int mode = (b >= NB_E);
    const int cb = mode ? (b - NB_E) : b;
    const int* __restrict__ deg = mode ? g_deg_v : g_deg_e;
    const int n = mode ? NV : NE;
    int start = cb * SCHUNK;
    int end = min(start + SCHUNK, n);
    int s = 0;
    for (int i = start + threadIdx.x; i < end; i += 256) s += deg[i];
#pragma unroll
    for (int d = 16; d; d >>= 1) s += __shfl_down_sync(0xFFFFFFFFu, s, d);
    __shared__ int ws[8];
    if ((threadIdx.x & 31) == 0) ws[threadIdx.x >> 5] = s;
    __syncthreads();
    if (threadIdx.x == 0) {
        int t = 0;
#pragma unroll
        for (int w = 0; w < 8; w++) t += ws[w];
        if (mode) g_bsum_v[cb] = t; else g_bsum_e[cb] = t;
    }
}
__global__ void k_scan_mid() {
    if (threadIdx.x == 0) {
        int run = 0;
        for (int i = 0; i < NB_E; i++) { int t = g_bsum_e[i]; g_bsum_e[i] = run; run += t; }
    } else if (threadIdx.x == 1) {
        int run = 0;
        for (int i = 0; i < NB_V; i++) { int t = g_bsum_v[i]; g_bsum_v[i] = run; run += t; }
    }
}
__global__ void k_scan_final() {
    int b = blockIdx.x;
    const int mode = (b >= NB_E);
    const int cb = mode ? (b - NB_E) : b;
    const int* __restrict__ deg = mode ? g_deg_v : g_deg_e;
    int* __restrict__ off       = mode ? g_off_v : g_off_e;
    const int n = mode ? NV : NE;
    const int tid  = threadIdx.x;
    const int lane = tid & 31;
    const int w    = tid >> 5;
    int start = cb * SCHUNK;
    int carry = mode ? g_bsum_v[cb] : g_bsum_e[cb];
    __shared__ int ws[8];
    __shared__ int btotal;
    for (int batch = 0; batch < SCHUNK / 256; batch++) {
        int i = start + batch * 256 + tid;
        int v = (i < n) ? deg[i] : 0;
        int s = v;
#pragma unroll
        for (int d = 1; d < 32; d <<= 1) {
            int t = __shfl_up_sync(0xFFFFFFFFu, s, d);
            if (lane >= d) s += t;
        }
        if (lane == 31) ws[w] = s;
        __syncthreads();
        if (tid == 0) {
            int run = 0;
#pragma unroll
            for (int j = 0; j < 8; j++) { int t = ws[j]; ws[j] = run; run += t; }
            btotal = run;
        }
        __syncthreads();
        s += ws[w];
        if (i < n) off[i] = carry + s - v;
        if (i == n - 1) off[n] = carry + s;
        carry += btotal;
        __syncthreads();
    }
}

// ---------------- CSR fill ----------------
__global__ void k_fill(const int* __restrict__ v_idx, const int* __restrict__ e_idx) {
    int i = blockIdx.x * blockDim.x + threadIdx.x;
    if (i < NM) {
        int v = v_idx[i];
        int e = e_idx[i];
        int pe = atomicAdd(&g_cur_e[e], 1);
        g_csr_e_v[g_off_e[e] + pe] = v;
        int pv = atomicAdd(&g_cur_v[v], 1);
        g_csr_v_e[g_off_v[v] + pv] = e;
    }
}

// ---------------- convert X to fp16 ----------------
__global__ void k_cvtX(const float* __restrict__ X) {
    long n4 = (long)NV * DD / 4;
    long stride = (long)gridDim.x * blockDim.x;
    for (long i4 = (long)blockIdx.x * blockDim.x + threadIdx.x; i4 < n4; i4 += stride) {
        float4 v = ((const float4*)X)[i4];
        __half2 h01 = __floats2half2_rn(v.x, v.y);
        __half2 h23 = __floats2half2_rn(v.z, v.w);
        ((__half2*)g_Xh)[i4 * 2 + 0] = h01;
        ((__half2*)g_Xh)[i4 * 2 + 1] = h23;
    }
}

// ---------------- transpose + convert W to fp16 ----------------
__global__ void k_cvtW(const float* __restrict__ W) {
    int i = blockIdx.x * blockDim.x + threadIdx.x;  // i = n*512 + k
    if (i < DD * DD) {
        int n = i >> 9, k = i & 511;
        g_Wth[i] = __float2half_rn(W[(size_t)k * DD + n]);
    }
}

// ---------------- fp16 GEMM: Y = Xh@Wh + b, fp16 Y out, stats fused --------
// Block 128x128, BK=32, 8 warps (64x32 warp tiles), 2 CTAs/SM, double buffered.
#define SPAD 40
#define TBUF (128 * SPAD * 2)               // 10240 bytes per tile buffer
#define GT_SMEM (4 * TBUF)                  // A,B double buffered = 40960
__global__ __launch_bounds__(256, 2) void k_gemm_mma(const float* __restrict__ bias) {
    extern __shared__ __align__(16) char dsm[];
    const uint32_t sb = smem_u32(dsm);
    const uint32_t aoff[2] = {sb,            sb + TBUF};
    const uint32_t boff[2] = {sb + 2 * TBUF, sb + 3 * TBUF};

    const int tid    = threadIdx.x;
    const int wid    = tid >> 5;
    const int lane   = tid & 31;
    const int warp_m = wid >> 2;   // 0..1
    const int warp_n = wid & 3;    // 0..3
    const int row0   = blockIdx.y * 128;
    const int n0     = blockIdx.x * 128;

    const int ld_r = tid >> 2;            // 0..63
    const int ld_q = (tid & 3) * 8;       // fp16 col within 32

    const int a_row = warp_m * 64 + (lane & 15);
    const int a_col = ((lane >> 4) << 3);
    const int b_row = warp_n * 32 + ((lane >> 4) << 3) + (lane & 7);
    const int b_col = ((lane >> 3) & 1) << 3;

    float acc[4][4][4];
#pragma unroll
    for (int i = 0; i < 4; i++)
#pragma unroll
        for (int j = 0; j < 4; j++)
#pragma unroll
            for (int r = 0; r < 4; r++) acc[i][j][r] = 0.0f;

    auto issue_tile = [&](int kt, int buf) {
        const int k0 = kt * 32;
#pragma unroll
        for (int i = 0; i < 2; i++) {
            int r = ld_r + i * 64;
            int gr = row0 + r;
            bool ok = gr < NV;
            int grc = ok ? gr : 0;
            cp16(aoff[buf] + (r * SPAD + ld_q) * 2, g_Xh + (size_t)grc * DD + k0 + ld_q, ok);
            cp16(boff[buf] + (r * SPAD + ld_q) * 2, g_Wth + (size_t)(n0 + r) * DD + k0 + ld_q, true);
        }
        cp_commit();
    };

    issue_tile(0, 0);
#pragma unroll 1
    for (int kt = 0; kt < 16; kt++) {
        const int buf = kt & 1;
        if (kt + 1 < 16) {
            issue_tile(kt + 1, buf ^ 1);
            cp_wait<1>();
        } else {
            cp_wait<0>();
        }
        __syncthreads();

#pragma unroll
        for (int k16 = 0; k16 < 2; k16++) {
            const int kk = k16 * 16;
            uint32_t a[4][4];
#pragma unroll
            for (int mt = 0; mt < 4; mt++)
                ldm_x4(a[mt], aoff[buf] + ((a_row + mt * 16) * SPAD + a_col + kk) * 2);
            uint32_t bf[2][4];
#pragma unroll
            for (int np = 0; np < 2; np++)
                ldm_x4(bf[np], boff[buf] + ((b_row + np * 16) * SPAD + b_col + kk) * 2);
#pragma unroll
            for (int mt = 0; mt < 4; mt++)
#pragma unroll
                for (int nt = 0; nt < 4; nt++)
                    mma16816(acc[mt][nt], a[mt], &bf[nt >> 1][(nt & 1) * 2]);
        }
        __syncthreads();
    }

    // ---- epilogue: bias add, store Y fp16, fused per-column stats ----
    const int mrow = lane >> 2;
    const int mcol = (lane & 3) * 2;
    float cs[4][2], cq[4][2];
#pragma unroll
    for (int nt = 0; nt < 4; nt++) {
        cs[nt][0] = cs[nt][1] = 0.0f;
        cq[nt][0] = cq[nt][1] = 0.0f;
    }
#pragma unroll
    for (int mt = 0; mt < 4; mt++) {
        int gr0 = row0 + warp_m * 64 + mt * 16 + mrow;
        int gr1 = gr0 + 8;
        bool ok0 = gr0 < NV, ok1 = gr1 < NV;
#pragma unroll
        for (int nt = 0; nt < 4; nt++) {
            int gc = n0 + warp_n * 32 + nt * 8 + mcol;
            float2 bb = *(const float2*)(bias + gc);
            if (ok0) {
                float ox = acc[mt][nt][0] + bb.x;
                float oy = acc[mt][nt][1] + bb.y;
                *(__half2*)(g_Yh + (size_t)gr0 * DD + gc) = __floats2half2_rn(ox, oy);
                cs[nt][0] += ox; cq[nt][0] += ox * ox;
                cs[nt][1] += oy; cq[nt][1] += oy * oy;
            }
            if (ok1) {
                float ox = acc[mt][nt][2] + bb.x;
                float oy = acc[mt][nt][3] + bb.y;
                *(__half2*)(g_Yh + (size_t)gr1 * DD + gc) = __floats2half2_rn(ox, oy);
                cs[nt][0] += ox; cq[nt][0] += ox * ox;
                cs[nt][1] += oy; cq[nt][1] += oy * oy;
            }
        }
    }
#pragma unroll
    for (int off = 16; off >= 4; off >>= 1) {
#pragma unroll
        for (int nt = 0; nt < 4; nt++) {
#pragma unroll
            for (int j = 0; j < 2; j++) {
                cs[nt][j] += __shfl_down_sync(0xFFFFFFFFu, cs[nt][j], off);
                cq[nt][j] += __shfl_down_sync(0xFFFFFFFFu, cq[nt][j], off);
            }
        }
    }
    if (lane < 4) {
#pragma unroll
        for (int nt = 0; nt < 4; nt++) {
#pragma unroll
            for (int j = 0; j < 2; j++) {
                int gc = n0 + warp_n * 32 + nt * 8 + lane * 2 + j;
                atomicAdd(&g_stats[gc], cs[nt][j]);
                atomicAdd(&g_stats[DD + gc], cq[nt][j]);
            }
        }
    }
}

// ---------------- finalize BN scale/shift ----------------
__global__ void k_finalize(const float* __restrict__ gamma, const float* __restrict__ beta) {
    int c = threadIdx.x;
    float mu  = g_stats[c] * (1.0f / NV);
    float var = g_stats[DD + c] * (1.0f / NV) - mu * mu;
    float rs  = rsqrtf(var + BN_EPS);
    float sc  = gamma[c] * rs;
    g_scale[c] = sc;
    g_shift[c] = beta[c] - mu * sc;
}

// ---------------- v2e (CSR gather from fp16 Y): HE = scale*mean+shift ----------------
__global__ __launch_bounds__(128) void k_v2e(float* __restrict__ HE) {
    int e  = blockIdx.x;
    int c4 = threadIdx.x * 4;
    int s = g_off_e[e], t = g_off_e[e + 1];
    float4 acc = make_float4(0.f, 0.f, 0.f, 0.f);
    int j = s;
    for (; j + 2 <= t; j += 2) {
        int v0 = g_csr_e_v[j + 0];
        int v1 = g_csr_e_v[j + 1];
        uint2 u0 = *(const uint2*)(g_Yh + (size_t)v0 * DD + c4);
        uint2 u1 = *(const uint2*)(g_Yh + (size_t)v1 * DD + c4);
        float2 a0 = __half22float2(*(__half2*)&u0.x);
        float2 a1 = __half22float2(*(__half2*)&u0.y);
        float2 b0 = __half22float2(*(__half2*)&u1.x);
        float2 b1 = __half22float2(*(__half2*)&u1.y);
        acc.x += a0.x + b0.x; acc.y += a0.y + b0.y;
        acc.z += a1.x + b1.x; acc.w += a1.y + b1.y;
    }
    for (; j < t; j++) {
        int v = g_csr_e_v[j];
        uint2 u = *(const uint2*)(g_Yh + (size_t)v * DD + c4);
        float2 a0 = __half22float2(*(__half2*)&u.x);
        float2 a1 = __half22float2(*(__half2*)&u.y);
        acc.x += a0.x; acc.y += a0.y; acc.z += a1.x; acc.w += a1.y;
    }
    float w = 1.0f / (float)max(t - s, 1);
    float4 sc = *(const float4*)(g_scale + c4);
    float4 sh = *(const float4*)(g_shift + c4);
    float4 o;
    o.x = fmaf(acc.x * w, sc.x, sh.x);
    o.y = fmaf(acc.y * w, sc.y, sh.y);
    o.z = fmaf(acc.z * w, sc.z, sh.z);
    o.w = fmaf(acc.w * w, sc.w, sh.w);
    *(float4*)(HE + (size_t)e * DD + c4) = o;
    // fp16 shadow for e2v gather
    __half2 h0 = __floats2half2_rn(o.x, o.y);
    __half2 h1 = __floats2half2_rn(o.z, o.w);
    uint2 hu;
    hu.x = *(uint32_t*)&h0;
    hu.y = *(uint32_t*)&h1;
    *(uint2*)(g_HEh + (size_t)e * DD + c4) = hu;
}

// ---------------- e2v (CSR gather from fp16 HE) ----------------
__global__ __launch_bounds__(128) void k_e2v(float* __restrict__ Xout) {
    int v  = blockIdx.x;
    int c4 = threadIdx.x * 4;
    int s = g_off_v[v], t = g_off_v[v + 1];
    float4 acc = make_float4(0.f, 0.f, 0.f, 0.f);
    int j = s;
    for (; j + 2 <= t; j += 2) {
        int e0 = g_csr_v_e[j + 0];
        int e1 = g_csr_v_e[j + 1];
        uint2 u0 = *(const uint2*)(g_HEh + (size_t)e0 * DD + c4);
        uint2 u1 = *(const uint2*)(g_HEh + (size_t)e1 * DD + c4);
        float2 a0 = __half22float2(*(__half2*)&u0.x);
        float2 a1 = __half22float2(*(__half2*)&u0.y);
        float2 b0 = __half22float2(*(__half2*)&u1.x);
        float2 b1 = __half22float2(*(__half2*)&u1.y);
        acc.x += a0.x + b0.x; acc.y += a0.y + b0.y;
        acc.z += a1.x + b1.x; acc.w += a1.y + b1.y;
    }
    for (; j < t; j++) {
        int e = g_csr_v_e[j];
        uint2 u = *(const uint2*)(g_HEh + (size_t)e * DD + c4);
        float2 a0 = __half22float2(*(__half2*)&u.x);
        float2 a1 = __half22float2(*(__half2*)&u.y);
        acc.x += a0.x; acc.y += a0.y; acc.z += a1.x; acc.w += a1.y;
    }
    float w = 1.0f / (float)max(t - s, 1);
    float4 o = make_float4(acc.x * w, acc.y * w, acc.z * w, acc.w * w);
    *(float4*)(Xout + (size_t)v * DD + c4) = o;
}

// ---------------- launcher ----------------
extern "C" void kernel_launch(void* const* d_in, const int* in_sizes, int n_in,
                              void* d_out, int out_size) {
    const float* X     = (const float*)d_in[0];
    const float* W     = (const float*)d_in[1];
    const float* b     = (const float*)d_in[2];
    const float* gamma = (const float*)d_in[3];
    const float* beta  = (const float*)d_in[4];
    const int* v_idx   = (const int*)d_in[5];
    const int* e_idx   = (const int*)d_in[6];

    float* Xout = (float*)d_out;
    float* HE   = Xout + (size_t)NV * DD;

    cudaFuncSetAttribute(k_gemm_mma, cudaFuncAttributeMaxDynamicSharedMemorySize, GT_SMEM);

    k_zero_misc<<<(NV + 255) / 256, 256>>>();
    long expected = (long)(NV + NE) * DD;
    if ((long)out_size > expected)
        k_zero<<<64, 256>>>(Xout + expected, (long)out_size - expected);

    // CSR build
    k_deg<<<(NM + 255) / 256, 256>>>(v_idx, e_idx);
    k_scan_part<<<NB_E + NB_V, 256>>>();
    k_scan_mid<<<1, 32>>>();
    k_scan_final<<<NB_E + NB_V, 256>>>();
    k_fill<<<(NM + 255) / 256, 256>>>(v_idx, e_idx);

    // precision prep
    k_cvtX<<<2048, 256>>>(X);
    k_cvtW<<<(DD * DD + 255) / 256, 256>>>(W);

    // fp16 tensor-core GEMM with fused BN stats, fp16 Y output
    dim3 gg(DD / 128, (NV + 127) / 128);
    k_gemm_mma<<<gg, 256, GT_SMEM>>>(b);
    k_finalize<<<1, DD>>>(gamma, beta);

    // gather-based segment means (fp16 sources)
    k_v2e<<<NE, 128>>>(HE);
    k_e2v<<<NV, 128>>>(Xout);
}

// round 10
// speedup vs baseline: 2.6006x; 1.1234x over previous
#include <cuda_runtime.h>
#include <cuda_fp16.h>
#include <cstdint>

#define NV 50000
#define NE 10000
#define NM 200000
#define DD 512
#define BN_EPS 1e-5f

// ---------------- scratch (static device globals; no allocation) ----------------
__device__ __half g_Yh[(size_t)NV * DD];   // GEMM output (pre-BN) in fp16
__device__ __half g_Xh[(size_t)NV * DD];   // X in fp16
__device__ __half g_Wth[DD * DD];          // W^T fp16   [n][k]
__device__ __half g_HEh[(size_t)NE * DD];  // HE shadow in fp16
__device__ float g_stats[2 * DD];
__device__ float g_scale[DD];
__device__ float g_shift[DD];
__device__ int   g_deg_e[NE];
__device__ int   g_deg_v[NV];
__device__ int   g_cur_e[NE];
__device__ int   g_cur_v[NV];
__device__ int   g_off_e[NE + 1];
__device__ int   g_off_v[NV + 1];
__device__ int   g_csr_e_v[NM];
__device__ int   g_csr_v_e[NM];
__device__ int   g_bsum_e[40];
__device__ int   g_bsum_v[40];

// ---------------- helpers ----------------
__device__ __forceinline__ uint32_t smem_u32(const void* p) {
    uint32_t a;
    asm("{ .reg .u64 t; cvta.to.shared.u64 t, %1; cvt.u32.u64 %0, t; }" : "=r"(a) : "l"(p));
    return a;
}
__device__ __forceinline__ void ldm_x4(uint32_t* r, uint32_t addr) {
    asm volatile("ldmatrix.sync.aligned.m8n8.x4.shared.b16 {%0,%1,%2,%3}, [%4];"
                 : "=r"(r[0]), "=r"(r[1]), "=r"(r[2]), "=r"(r[3]) : "r"(addr));
}
__device__ __forceinline__ void mma16816(float* d, const uint32_t* a, const uint32_t* b) {
    asm volatile(
        "mma.sync.aligned.m16n8k16.row.col.f32.f16.f16.f32 "
        "{%0,%1,%2,%3}, {%4,%5,%6,%7}, {%8,%9}, {%0,%1,%2,%3};"
        : "+f"(d[0]), "+f"(d[1]), "+f"(d[2]), "+f"(d[3])
        : "r"(a[0]), "r"(a[1]), "r"(a[2]), "r"(a[3]), "r"(b[0]), "r"(b[1]));
}
__device__ __forceinline__ void cp16(uint32_t saddr, const void* g, bool pred) {
    int sz = pred ? 16 : 0;
    asm volatile("cp.async.cg.shared.global [%0], [%1], 16, %2;"
                 :: "r"(saddr), "l"(g), "r"(sz) : "memory");
}
__device__ __forceinline__ void cp_commit() {
    asm volatile("cp.async.commit_group;" ::: "memory");
}
template <int N>
__device__ __forceinline__ void cp_wait() {
    asm volatile("cp.async.wait_group %0;" :: "n"(N) : "memory");
}

// ---------------- zeroing ----------------
__global__ void k_zero(float* p, long n) {
    long stride = (long)gridDim.x * blockDim.x;
    for (long i = (long)blockIdx.x * blockDim.x + threadIdx.x; i < n; i += stride)
        p[i] = 0.0f;
}
__global__ void k_zero_misc() {
    int i = blockIdx.x * blockDim.x + threadIdx.x;
    if (i < 2 * DD) g_stats[i] = 0.0f;
    if (i < NE) { g_deg_e[i] = 0; g_cur_e[i] = 0; }
    if (i < NV) { g_deg_v[i] = 0; g_cur_v[i] = 0; }
}

// ---------------- degree counting ----------------
__global__ void k_deg(const int* __restrict__ v_idx, const int* __restrict__ e_idx) {
    int i = blockIdx.x * blockDim.x + threadIdx.x;
    if (i < NM) {
        atomicAdd(&g_deg_v[v_idx[i]], 1);
        atomicAdd(&g_deg_e[e_idx[i]], 1);
    }
}

// ---------------- multi-block exclusive scan (both arrays in one grid) ----------------
#define SCHUNK 2048
#define NB_E ((NE + SCHUNK - 1) / SCHUNK)   // 5
#define NB_V ((NV + SCHUNK - 1) / SCHUNK)   // 25
__global__ void k_scan_part() {
    int b = blockIdx.x;
    const int mode = (b >= NB_E);
    const int cb = mode ? (b - NB_E) : b;
    const int* __restrict__ deg = mode ? g_deg_v : g_deg_e;
    const int n = mode ? NV : NE;
    int start = cb * SCHUNK;
    int end = min(start + SCHUNK, n);
    int s = 0;
    for (int i = start + threadIdx.x; i < end; i += 256) s += deg[i];
#pragma unroll
    for (int d = 16; d; d >>= 1) s += __shfl_down_sync(0xFFFFFFFFu, s, d);
    __shared__ int ws[8];
    if ((threadIdx.x & 31) == 0) ws[threadIdx.x >> 5] = s;
    __syncthreads();
    if (threadIdx.x == 0) {
        int t = 0;
#pragma unroll
        for (int w = 0; w < 8; w++) t += ws[w];
        if (mode) g_bsum_v[cb] = t; else g_bsum_e[cb] = t;
    }
}
__global__ void k_scan_mid() {
    if (threadIdx.x == 0) {
        int run = 0;
        for (int i = 0; i < NB_E; i++) { int t = g_bsum_e[i]; g_bsum_e[i] = run; run += t; }
    } else if (threadIdx.x == 1) {
        int run = 0;
        for (int i = 0; i < NB_V; i++) { int t = g_bsum_v[i]; g_bsum_v[i] = run; run += t; }
    }
}
__global__ void k_scan_final() {
    int b = blockIdx.x;
    const int mode = (b >= NB_E);
    const int cb = mode ? (b - NB_E) : b;
    const int* __restrict__ deg = mode ? g_deg_v : g_deg_e;
    int* __restrict__ off       = mode ? g_off_v : g_off_e;
    const int n = mode ? NV : NE;
    const int tid  = threadIdx.x;
    const int lane = tid & 31;
    const int w    = tid >> 5;
    int start = cb * SCHUNK;
    int carry = mode ? g_bsum_v[cb] : g_bsum_e[cb];
    __shared__ int ws[8];
    __shared__ int btotal;
    for (int batch = 0; batch < SCHUNK / 256; batch++) {
        int i = start + batch * 256 + tid;
        int v = (i < n) ? deg[i] : 0;
        int s = v;
#pragma unroll
        for (int d = 1; d < 32; d <<= 1) {
            int t = __shfl_up_sync(0xFFFFFFFFu, s, d);
            if (lane >= d) s += t;
        }
        if (lane == 31) ws[w] = s;
        __syncthreads();
        if (tid == 0) {
            int run = 0;
#pragma unroll
            for (int j = 0; j < 8; j++) { int t = ws[j]; ws[j] = run; run += t; }
            btotal = run;
        }
        __syncthreads();
        s += ws[w];
        if (i < n) off[i] = carry + s - v;
        if (i == n - 1) off[n] = carry + s;
        carry += btotal;
        __syncthreads();
    }
}

// ---------------- CSR fill ----------------
__global__ void k_fill(const int* __restrict__ v_idx, const int* __restrict__ e_idx) {
    int i = blockIdx.x * blockDim.x + threadIdx.x;
    if (i < NM) {
        int v = v_idx[i];
        int e = e_idx[i];
        int pe = atomicAdd(&g_cur_e[e], 1);
        g_csr_e_v[g_off_e[e] + pe] = v;
        int pv = atomicAdd(&g_cur_v[v], 1);
        g_csr_v_e[g_off_v[v] + pv] = e;
    }
}

// ---------------- convert X to fp16 ----------------
__global__ void k_cvtX(const float* __restrict__ X) {
    long n4 = (long)NV * DD / 4;
    long stride = (long)gridDim.x * blockDim.x;
    for (long i4 = (long)blockIdx.x * blockDim.x + threadIdx.x; i4 < n4; i4 += stride) {
        float4 v = ((const float4*)X)[i4];
        __half2 h01 = __floats2half2_rn(v.x, v.y);
        __half2 h23 = __floats2half2_rn(v.z, v.w);
        ((__half2*)g_Xh)[i4 * 2 + 0] = h01;
        ((__half2*)g_Xh)[i4 * 2 + 1] = h23;
    }
}

// ---------------- transpose + convert W to fp16 ----------------
__global__ void k_cvtW(const float* __restrict__ W) {
    int i = blockIdx.x * blockDim.x + threadIdx.x;  // i = n*512 + k
    if (i < DD * DD) {
        int n = i >> 9, k = i & 511;
        g_Wth[i] = __float2half_rn(W[(size_t)k * DD + n]);
    }
}

// ---------------- fp16 GEMM: Y = Xh@Wh + b, fp16 Y out, stats fused --------
// Block 128x128, BK=32, 8 warps, 2 CTAs/SM, 3-stage cp.async pipeline, 1 sync/iter.
#define SPAD 40
#define TBUF (128 * SPAD * 2)               // 10240 bytes per tile buffer
#define GT_SMEM (6 * TBUF)                  // A,B x 3 stages = 61440
__global__ __launch_bounds__(256, 2) void k_gemm_mma(const float* __restrict__ bias) {
    extern __shared__ __align__(16) char dsm[];
    const uint32_t sb = smem_u32(dsm);
    const uint32_t aoff[3] = {sb,            sb + 2 * TBUF, sb + 4 * TBUF};
    const uint32_t boff[3] = {sb + TBUF,     sb + 3 * TBUF, sb + 5 * TBUF};

    const int tid    = threadIdx.x;
    const int wid    = tid >> 5;
    const int lane   = tid & 31;
    const int warp_m = wid >> 2;   // 0..1
    const int warp_n = wid & 3;    // 0..3
    const int row0   = blockIdx.y * 128;
    const int n0     = blockIdx.x * 128;

    const int ld_r = tid >> 2;            // 0..63
    const int ld_q = (tid & 3) * 8;       // fp16 col within 32

    const int a_row = warp_m * 64 + (lane & 15);
    const int a_col = ((lane >> 4) << 3);
    const int b_row = warp_n * 32 + ((lane >> 4) << 3) + (lane & 7);
    const int b_col = ((lane >> 3) & 1) << 3;

    float acc[4][4][4];
#pragma unroll
    for (int i = 0; i < 4; i++)
#pragma unroll
        for (int j = 0; j < 4; j++)
#pragma unroll
            for (int r = 0; r < 4; r++) acc[i][j][r] = 0.0f;

    auto issue_tile = [&](int kt, int st) {
        const int k0 = kt * 32;
#pragma unroll
        for (int i = 0; i < 2; i++) {
            int r = ld_r + i * 64;
            int gr = row0 + r;
            bool ok = gr < NV;
            int grc = ok ? gr : 0;
            cp16(aoff[st] + (r * SPAD + ld_q) * 2, g_Xh + (size_t)grc * DD + k0 + ld_q, ok);
            cp16(boff[st] + (r * SPAD + ld_q) * 2, g_Wth + (size_t)(n0 + r) * DD + k0 + ld_q, true);
        }
        cp_commit();
    };

    issue_tile(0, 0);
    issue_tile(1, 1);
#pragma unroll 1
    for (int kt = 0; kt < 16; kt++) {
        if (kt + 1 < 16) cp_wait<1>(); else cp_wait<0>();
        __syncthreads();
        const int st = kt % 3;

#pragma unroll
        for (int k16 = 0; k16 < 2; k16++) {
            const int kk = k16 * 16;
            uint32_t a[4][4];
#pragma unroll
            for (int mt = 0; mt < 4; mt++)
                ldm_x4(a[mt], aoff[st] + ((a_row + mt * 16) * SPAD + a_col + kk) * 2);
            uint32_t bf[2][4];
#pragma unroll
            for (int np = 0; np < 2; np++)
                ldm_x4(bf[np], boff[st] + ((b_row + np * 16) * SPAD + b_col + kk) * 2);
#pragma unroll
            for (int mt = 0; mt < 4; mt++)
#pragma unroll
                for (int nt = 0; nt < 4; nt++)
                    mma16816(acc[mt][nt], a[mt], &bf[nt >> 1][(nt & 1) * 2]);
        }
        if (kt + 2 < 16) issue_tile(kt + 2, (kt + 2) % 3);
    }

    // ---- epilogue: bias add, store Y fp16, fused per-column stats ----
    const int mrow = lane >> 2;
    const int mcol = (lane & 3) * 2;
    float cs[4][2], cq[4][2];
#pragma unroll
    for (int nt = 0; nt < 4; nt++) {
        cs[nt][0] = cs[nt][1] = 0.0f;
        cq[nt][0] = cq[nt][1] = 0.0f;
    }
#pragma unroll
    for (int mt = 0; mt < 4; mt++) {
        int gr0 = row0 + warp_m * 64 + mt * 16 + mrow;
        int gr1 = gr0 + 8;
        bool ok0 = gr0 < NV, ok1 = gr1 < NV;
#pragma unroll
        for (int nt = 0; nt < 4; nt++) {
            int gc = n0 + warp_n * 32 + nt * 8 + mcol;
            float2 bb = *(const float2*)(bias + gc);
            if (ok0) {
                float ox = acc[mt][nt][0] + bb.x;
                float oy = acc[mt][nt][1] + bb.y;
                *(__half2*)(g_Yh + (size_t)gr0 * DD + gc) = __floats2half2_rn(ox, oy);
                cs[nt][0] += ox; cq[nt][0] += ox * ox;
                cs[nt][1] += oy; cq[nt][1] += oy * oy;
            }
            if (ok1) {
                float ox = acc[mt][nt][2] + bb.x;
                float oy = acc[mt][nt][3] + bb.y;
                *(__half2*)(g_Yh + (size_t)gr1 * DD + gc) = __floats2half2_rn(ox, oy);
                cs[nt][0] += ox; cq[nt][0] += ox * ox;
                cs[nt][1] += oy; cq[nt][1] += oy * oy;
            }
        }
    }
#pragma unroll
    for (int off = 16; off >= 4; off >>= 1) {
#pragma unroll
        for (int nt = 0; nt < 4; nt++) {
#pragma unroll
            for (int j = 0; j < 2; j++) {
                cs[nt][j] += __shfl_down_sync(0xFFFFFFFFu, cs[nt][j], off);
                cq[nt][j] += __shfl_down_sync(0xFFFFFFFFu, cq[nt][j], off);
            }
        }
    }
    if (lane < 4) {
#pragma unroll
        for (int nt = 0; nt < 4; nt++) {
#pragma unroll
            for (int j = 0; j < 2; j++) {
                int gc = n0 + warp_n * 32 + nt * 8 + lane * 2 + j;
                atomicAdd(&g_stats[gc], cs[nt][j]);
                atomicAdd(&g_stats[DD + gc], cq[nt][j]);
            }
        }
    }
}

// ---------------- finalize BN scale/shift ----------------
__global__ void k_finalize(const float* __restrict__ gamma, const float* __restrict__ beta) {
    int c = threadIdx.x;
    float mu  = g_stats[c] * (1.0f / NV);
    float var = g_stats[DD + c] * (1.0f / NV) - mu * mu;
    float rs  = rsqrtf(var + BN_EPS);
    float sc  = gamma[c] * rs;
    g_scale[c] = sc;
    g_shift[c] = beta[c] - mu * sc;
}

// ---------------- v2e (CSR gather from fp16 Y): HE = scale*mean+shift ----------------
__global__ __launch_bounds__(128) void k_v2e(float* __restrict__ HE) {
    int e  = blockIdx.x;
    int c4 = threadIdx.x * 4;
    int s = g_off_e[e], t = g_off_e[e + 1];
    float4 acc = make_float4(0.f, 0.f, 0.f, 0.f);
    int j = s;
    for (; j + 2 <= t; j += 2) {
        int v0 = g_csr_e_v[j + 0];
        int v1 = g_csr_e_v[j + 1];
        uint2 u0 = *(const uint2*)(g_Yh + (size_t)v0 * DD + c4);
        uint2 u1 = *(const uint2*)(g_Yh + (size_t)v1 * DD + c4);
        float2 a0 = __half22float2(*(__half2*)&u0.x);
        float2 a1 = __half22float2(*(__half2*)&u0.y);
        float2 b0 = __half22float2(*(__half2*)&u1.x);
        float2 b1 = __half22float2(*(__half2*)&u1.y);
        acc.x += a0.x + b0.x; acc.y += a0.y + b0.y;
        acc.z += a1.x + b1.x; acc.w += a1.y + b1.y;
    }
    for (; j < t; j++) {
        int v = g_csr_e_v[j];
        uint2 u = *(const uint2*)(g_Yh + (size_t)v * DD + c4);
        float2 a0 = __half22float2(*(__half2*)&u.x);
        float2 a1 = __half22float2(*(__half2*)&u.y);
        acc.x += a0.x; acc.y += a0.y; acc.z += a1.x; acc.w += a1.y;
    }
    float w = 1.0f / (float)max(t - s, 1);
    float4 sc = *(const float4*)(g_scale + c4);
    float4 sh = *(const float4*)(g_shift + c4);
    float4 o;
    o.x = fmaf(acc.x * w, sc.x, sh.x);
    o.y = fmaf(acc.y * w, sc.y, sh.y);
    o.z = fmaf(acc.z * w, sc.z, sh.z);
    o.w = fmaf(acc.w * w, sc.w, sh.w);
    *(float4*)(HE + (size_t)e * DD + c4) = o;
    __half2 h0 = __floats2half2_rn(o.x, o.y);
    __half2 h1 = __floats2half2_rn(o.z, o.w);
    uint2 hu;
    hu.x = *(uint32_t*)&h0;
    hu.y = *(uint32_t*)&h1;
    *(uint2*)(g_HEh + (size_t)e * DD + c4) = hu;
}

// ---------------- e2v (CSR gather from fp16 HE) ----------------
__global__ __launch_bounds__(128) void k_e2v(float* __restrict__ Xout) {
    int v  = blockIdx.x;
    int c4 = threadIdx.x * 4;
    int s = g_off_v[v], t = g_off_v[v + 1];
    float4 acc = make_float4(0.f, 0.f, 0.f, 0.f);
    int j = s;
    for (; j + 2 <= t; j += 2) {
        int e0 = g_csr_v_e[j + 0];
        int e1 = g_csr_v_e[j + 1];
        uint2 u0 = *(const uint2*)(g_HEh + (size_t)e0 * DD + c4);
        uint2 u1 = *(const uint2*)(g_HEh + (size_t)e1 * DD + c4);
        float2 a0 = __half22float2(*(__half2*)&u0.x);
        float2 a1 = __half22float2(*(__half2*)&u0.y);
        float2 b0 = __half22float2(*(__half2*)&u1.x);
        float2 b1 = __half22float2(*(__half2*)&u1.y);
        acc.x += a0.x + b0.x; acc.y += a0.y + b0.y;
        acc.z += a1.x + b1.x; acc.w += a1.y + b1.y;
    }
    for (; j < t; j++) {
        int e = g_csr_v_e[j];
        uint2 u = *(const uint2*)(g_HEh + (size_t)e * DD + c4);
        float2 a0 = __half22float2(*(__half2*)&u.x);
        float2 a1 = __half22float2(*(__half2*)&u.y);
        acc.x += a0.x; acc.y += a0.y; acc.z += a1.x; acc.w += a1.y;
    }
    float w = 1.0f / (float)max(t - s, 1);
    float4 o = make_float4(acc.x * w, acc.y * w, acc.z * w, acc.w * w);
    *(float4*)(Xout + (size_t)v * DD + c4) = o;
}

// ---------------- launcher ----------------
extern "C" void kernel_launch(void* const* d_in, const int* in_sizes, int n_in,
                              void* d_out, int out_size) {
    const float* X     = (const float*)d_in[0];
    const float* W     = (const float*)d_in[1];
    const float* b     = (const float*)d_in[2];
    const float* gamma = (const float*)d_in[3];
    const float* beta  = (const float*)d_in[4];
    const int* v_idx   = (const int*)d_in[5];
    const int* e_idx   = (const int*)d_in[6];

    float* Xout = (float*)d_out;
    float* HE   = Xout + (size_t)NV * DD;

    // one-time host-side setup (no device memory involved)
    static cudaStream_t s2 = nullptr;
    static cudaEvent_t evFork = nullptr, evJoin = nullptr;
    if (s2 == nullptr) {
        cudaStreamCreateWithFlags(&s2, cudaStreamNonBlocking);
        cudaEventCreateWithFlags(&evFork, cudaEventDisableTiming);
        cudaEventCreateWithFlags(&evJoin, cudaEventDisableTiming);
        cudaFuncSetAttribute(k_gemm_mma, cudaFuncAttributeMaxDynamicSharedMemorySize, GT_SMEM);
    }

    // common prologue on main stream (zeroes stats + degree/cursor arrays)
    k_zero_misc<<<(NV + 255) / 256, 256>>>();
    long expected = (long)(NV + NE) * DD;
    if ((long)out_size > expected)
        k_zero<<<64, 256>>>(Xout + expected, (long)out_size - expected);

    // ---- fork: CSR build on side stream ----
    cudaEventRecord(evFork, 0);
    cudaStreamWaitEvent(s2, evFork, 0);
    k_deg<<<(NM + 255) / 256, 256, 0, s2>>>(v_idx, e_idx);
    k_scan_part<<<NB_E + NB_V, 256, 0, s2>>>();
    k_scan_mid<<<1, 32, 0, s2>>>();
    k_scan_final<<<NB_E + NB_V, 256, 0, s2>>>();
    k_fill<<<(NM + 255) / 256, 256, 0, s2>>>(v_idx, e_idx);
    cudaEventRecord(evJoin, s2);

    // ---- main stream: precision prep + GEMM + BN finalize ----
    k_cvtX<<<2048, 256>>>(X);
    k_cvtW<<<(DD * DD + 255) / 256, 256>>>(W);
    dim3 gg(DD / 128, (NV + 127) / 128);
    k_gemm_mma<<<gg, 256, GT_SMEM>>>(b);
    k_finalize<<<1, DD>>>(gamma, beta);

    // ---- join: gathers need CSR + finalize + Yh ----
    cudaStreamWaitEvent(0, evJoin, 0);
    k_v2e<<<NE, 128>>>(HE);
    k_e2v<<<NV, 128>>>(Xout);
}